// round 14
// baseline (speedup 1.0000x reference)
#include <cuda_runtime.h>
#include <math.h>

#define BB 2
#define C 19
#define CP 20             // padded channels
#define H 128
#define W 128
#define HW (H*W)          // 16384
#define CF 256
#define SH 64
#define SW 64
#define SP (SH*SW)        // 4096
#define N2 (BB*SP)        // 8192
#define NPIX (BB*HW)      // 32768
#define NCHUNK 8          // feature channel chunks of 32
#define NBLK 128          // phase-3 blocks
#define GRID 384
#define BAR_A_TARGET 384
#define BAR_B_TARGET 288

// Scratch (static device globals; no allocations)
__device__ float  g_prob2[NPIX*CP];      // padded probs [pixel][20], [19]=0
__device__ float  g_spart[NCHUNK*5*N2];  // [chunk*5+dir][b*SP+s]
__device__ float  g_sim[9*N2];           // [k][b*SP+s]
__device__ float  g_pos[6*NPIX];         // planes: 0=selfdot 1=E 2=SW 3=S 4=SE 5=sump
__device__ double g_partial[3*NBLK];
__device__ int    g_count = 0;
__device__ int    g_barA = 0;
__device__ int    g_barB = 0;

// ---- grid barrier primitives (counters reset by final block) ----
__device__ __forceinline__ void bar_arrive(int* bar) {
    __threadfence();                 // make this thread's stores visible (L2)
    __syncthreads();                 // all threads' work + fences done
    if (threadIdx.x == 0) atomicAdd(bar, 1);
}
__device__ __forceinline__ void bar_wait(int* bar, int target) {
    if (threadIdx.x == 0) {
        volatile int* vb = bar;
        while (*vb < target) __nanosleep(32);
    }
    __syncthreads();
}

// ================= phase 1: softmax || simpart =================
__device__ __forceinline__ void softmax_work(const float* __restrict__ logits, int idx) {
    int b = idx >> 14;
    int p = idx & (HW - 1);
    const float* x = logits + (size_t)b * C * HW + p;
    float v[CP];
    float m = -1e30f;
    #pragma unroll
    for (int c = 0; c < C; c++) { v[c] = x[(size_t)c * HW]; m = fmaxf(m, v[c]); }
    float s = 0.f;
    #pragma unroll
    for (int c = 0; c < C; c++) { v[c] = expf(v[c] - m); s += v[c]; }
    float inv = 1.f / s;
    #pragma unroll
    for (int c = 0; c < C; c++) v[c] *= inv;
    v[19] = 0.f;
    float4* o = reinterpret_cast<float4*>(g_prob2 + (size_t)idx * CP);
    #pragma unroll
    for (int q = 0; q < 5; q++)
        o[q] = make_float4(v[4*q], v[4*q+1], v[4*q+2], v[4*q+3]);
}

__device__ __forceinline__ void simpart_work(const float* __restrict__ feats,
                                             int idx, int chunk) {
    int b  = idx >> 12;
    int s  = idx & (SP - 1);
    int sh = s >> 6, sw = s & 63;

    bool eOK = (sw < SW-1), sOK = (sh < SH-1), wOK = (sw > 0);
    int dE  = eOK ? 1 : 0;
    int dSW = (sOK && wOK) ? (SW - 1) : 0;
    int dS  = sOK ? SW : 0;
    int dSE = (sOK && eOK) ? (SW + 1) : 0;

    const float* fb = feats + ((size_t)b * CF + chunk * 32) * SP + s;
    float a0 = 0.f, a1 = 0.f, a2 = 0.f, a3 = 0.f, a4 = 0.f;
    #pragma unroll
    for (int ch = 0; ch < 32; ch++) {
        const float* fp = fb + (size_t)ch * SP;
        float f = fp[0];
        float d;
        a0 += f * f;
        d = f - fp[dE];  a1 += d * d;
        d = f - fp[dSW]; a2 += d * d;
        d = f - fp[dS];  a3 += d * d;
        d = f - fp[dSE]; a4 += d * d;
    }
    g_spart[(chunk*5 + 0) * N2 + idx] = a0;
    g_spart[(chunk*5 + 1) * N2 + idx] = a1;
    g_spart[(chunk*5 + 2) * N2 + idx] = a2;
    g_spart[(chunk*5 + 3) * N2 + idx] = a3;
    g_spart[(chunk*5 + 4) * N2 + idx] = a4;
}

// ================= phase 2: posdots || simfin =================
__device__ __forceinline__ float dot20(const float4* pc, int nidx) {
    const float4* qv = reinterpret_cast<const float4*>(g_prob2 + (size_t)nidx * CP);
    float d = 0.f;
    #pragma unroll
    for (int u = 0; u < 5; u++) {
        float4 qq = qv[u];
        d += pc[u].x*qq.x + pc[u].y*qq.y + pc[u].z*qq.z + pc[u].w*qq.w;
    }
    return d;
}

__device__ __forceinline__ void pos_work(int t) {
    int half = t >> 15;
    int idx  = t & (NPIX - 1);
    int p = idx & (HW - 1);
    int h = p >> 7, w = p & 127;

    const float4* cen = reinterpret_cast<const float4*>(g_prob2 + (size_t)idx * CP);
    float4 pc[5];
    #pragma unroll
    for (int u = 0; u < 5; u++) pc[u] = cen[u];

    if (half == 0) {
        float sump = 0.f, cdot = 0.f;
        #pragma unroll
        for (int u = 0; u < 5; u++) {
            sump += pc[u].x + pc[u].y + pc[u].z + pc[u].w;
            cdot += pc[u].x*pc[u].x + pc[u].y*pc[u].y + pc[u].z*pc[u].z + pc[u].w*pc[u].w;
        }
        g_pos[0*NPIX + idx] = cdot;
        g_pos[5*NPIX + idx] = sump;
        g_pos[1*NPIX + idx] = (w < W-1)           ? dot20(pc, idx + 1)     : 0.f;
        g_pos[2*NPIX + idx] = (h < H-1 && w > 0)  ? dot20(pc, idx + W - 1) : 0.f;
    } else {
        g_pos[3*NPIX + idx] = (h < H-1)            ? dot20(pc, idx + W)     : 0.f;
        g_pos[4*NPIX + idx] = (h < H-1 && w < W-1) ? dot20(pc, idx + W + 1) : 0.f;
    }
}

__device__ __forceinline__ void simfin_work(int idx) {
    int s  = idx & (SP - 1);
    int sh = s >> 6, sw = s & 63;

    float self = 0.f, fE = 0.f, fSW = 0.f, fS = 0.f, fSE = 0.f;
    #pragma unroll
    for (int cu = 0; cu < NCHUNK; cu++) {
        self += g_spart[(cu*5 + 0) * N2 + idx];
        fE   += g_spart[(cu*5 + 1) * N2 + idx];
        fSW  += g_spart[(cu*5 + 2) * N2 + idx];
        fS   += g_spart[(cu*5 + 3) * N2 + idx];
        fSE  += g_spart[(cu*5 + 4) * N2 + idx];
    }
    bool wOK = (sw > 0), eOK = (sw < SW-1), nOK = (sh > 0), sOK = (sh < SH-1);

    float bW = 0.f, bNE = 0.f, bN = 0.f, bNW = 0.f;
    #pragma unroll
    for (int cu = 0; cu < NCHUNK; cu++) {
        if (wOK)         bW  += g_spart[(cu*5 + 1) * N2 + idx - 1];
        if (nOK && eOK)  bNE += g_spart[(cu*5 + 2) * N2 + idx - SW + 1];
        if (nOK)         bN  += g_spart[(cu*5 + 3) * N2 + idx - SW];
        if (nOK && wOK)  bNW += g_spart[(cu*5 + 4) * N2 + idx - SW - 1];
    }
    g_sim[4*N2 + idx] = expf(-self);
    g_sim[5*N2 + idx] = eOK          ? expf(-fE)  : 0.f;
    g_sim[6*N2 + idx] = (sOK && wOK) ? expf(-fSW) : 0.f;
    g_sim[7*N2 + idx] = sOK          ? expf(-fS)  : 0.f;
    g_sim[8*N2 + idx] = (sOK && eOK) ? expf(-fSE) : 0.f;
    g_sim[3*N2 + idx] = wOK          ? expf(-bW)  : 0.f;
    g_sim[2*N2 + idx] = (nOK && eOK) ? expf(-bNE) : 0.f;
    g_sim[1*N2 + idx] = nOK          ? expf(-bN)  : 0.f;
    g_sim[0*N2 + idx] = (nOK && wOK) ? expf(-bNW) : 0.f;
}

// ================= fused kernel =================
__global__ void __launch_bounds__(256, 3)
k_fused(const float* __restrict__ logits,
        const float* __restrict__ ori,
        float* __restrict__ out) {
    int tid = threadIdx.x;
    int bid = blockIdx.x;

    // ---------- phase 1 ----------
    if (bid < 128) {
        softmax_work(logits, bid * 256 + tid);
    } else {
        int sblk = bid - 128;                 // 0..255
        int xb = sblk & 31, chunk = sblk >> 5;
        simpart_work(ori, xb * 256 + tid, chunk);
    }

    // ---------- barrier A ----------
    bar_arrive(&g_barA);
    if (bid >= 288) return;                   // arrived; no further work
    bar_wait(&g_barA, BAR_A_TARGET);

    // ---------- phase 2 ----------
    if (bid < 256) pos_work(bid * 256 + tid);
    else           simfin_work((bid - 256) * 256 + tid);

    // ---------- barrier B ----------
    bar_arrive(&g_barB);
    if (bid >= 128) return;                   // arrived; no further work
    bar_wait(&g_barB, BAR_B_TARGET);

    // ---------- phase 3: main + fused final ----------
    __shared__ float rp[256], rn[256], rc[256];
    __shared__ int   sh_last;

    int idx = bid * 256 + tid;                // pixel index
    int b = idx >> 14;
    int p = idx & (HW - 1);
    int h = p >> 7, w = p & 127;
    int sh2 = h >> 1, sw2 = w >> 1;
    size_t sbase = (size_t)b * SP + sh2 * SW + sw2;

    bool nOKp = (h > 0), sOKp = (h < H-1), wOKp = (w > 0), eOKp = (w < W-1);

    float sump = g_pos[5*NPIX + idx];
    float pos[9];
    pos[4] = g_pos[0*NPIX + idx];
    pos[5] = eOKp          ? g_pos[1*NPIX + idx]         : 0.f;
    pos[3] = wOKp          ? g_pos[1*NPIX + idx - 1]     : 0.f;
    pos[7] = sOKp          ? g_pos[3*NPIX + idx]         : 0.f;
    pos[1] = nOKp          ? g_pos[3*NPIX + idx - W]     : 0.f;
    pos[6] = (sOKp && wOKp)? g_pos[2*NPIX + idx]         : 0.f;
    pos[2] = (nOKp && eOKp)? g_pos[2*NPIX + idx - W + 1] : 0.f;
    pos[8] = (sOKp && eOKp)? g_pos[4*NPIX + idx]         : 0.f;
    pos[0] = (nOKp && wOKp)? g_pos[4*NPIX + idx - W - 1] : 0.f;

    float simC = g_sim[4*N2 + sbase];
    float sim[9], neg[9];
    #pragma unroll
    for (int k = 0; k < 9; k++) {
        int dr = k / 3 - 1, dc = k % 3 - 1;
        int hn = h + dr, wn = w + dc;
        bool valid = (hn >= 0 && hn < H && wn >= 0 && wn < W);
        neg[k] = valid ? (sump - pos[k]) : 0.f;   // sumq==1 valid, 0 for pad
        if (valid) {
            int dsh = (hn >> 1) - sh2, dsw = (wn >> 1) - sw2;
            int ks = (dsh + 1) * 3 + (dsw + 1);
            sim[k] = (ks == 4) ? 1.0f : g_sim[ks * N2 + sbase];
        } else {
            sim[k] = simC;
        }
    }

    float ssum = 0.f;
    #pragma unroll
    for (int k = 0; k < 9; k++) ssum += sim[k];
    out[2 + idx] = ssum * (1.f / 9.f);

    // rank-based stable top-k (jax tie-breaking: lower index first)
    int r[9], a[9];
    #pragma unroll
    for (int k = 0; k < 9; k++) { r[k] = 0; a[k] = 0; }
    #pragma unroll
    for (int jj = 0; jj < 9; jj++) {
        #pragma unroll
        for (int kk = jj + 1; kk < 9; kk++) {
            bool l = sim[jj] < sim[kk];
            bool g = sim[jj] > sim[kk];
            r[kk] += !l;
            r[jj] += l;
            a[kk] += !g;
            a[jj] += g;
        }
    }
    float lp = 0.f, ln = 0.f;
    #pragma unroll
    for (int k = 0; k < 9; k++) {
        if (r[k] < 5) lp += sim[k] * (-pos[k]);
        if (a[k] < 4) ln += (1.f - sim[k]) * (-neg[k]);
    }

    float f0  = ori[(size_t)b * CF * SP + sh2 * SW + sw2];
    float msk = (f0 > 0.f) ? 1.f : 0.f;

    rp[tid] = msk * lp; rn[tid] = msk * ln; rc[tid] = msk;
    __syncthreads();
    #pragma unroll
    for (int o = 128; o > 0; o >>= 1) {
        if (tid < o) { rp[tid] += rp[tid + o]; rn[tid] += rn[tid + o]; rc[tid] += rc[tid + o]; }
        __syncthreads();
    }
    if (tid == 0) {
        g_partial[bid]            = (double)rp[0];
        g_partial[NBLK + bid]     = (double)rn[0];
        g_partial[2 * NBLK + bid] = (double)rc[0];
        __threadfence();
        int v = atomicAdd(&g_count, 1);
        sh_last = (v == NBLK - 1) ? 1 : 0;
    }
    __syncthreads();

    if (sh_last) {
        __shared__ double dp[128], dn[128], dc2[128];
        if (tid < 128) {
            volatile double* gp = g_partial;
            dp[tid]  = gp[tid];
            dn[tid]  = gp[NBLK + tid];
            dc2[tid] = gp[2 * NBLK + tid];
        }
        __syncthreads();
        #pragma unroll
        for (int o = 64; o > 0; o >>= 1) {
            if (tid < o) { dp[tid] += dp[tid + o]; dn[tid] += dn[tid + o]; dc2[tid] += dc2[tid + o]; }
            __syncthreads();
        }
        if (tid == 0) {
            double cnt = dc2[0];
            out[0] = (float)(dp[0] / (cnt * 5.0));   // /(cnt*(TOP_K+1)) * W_POS
            out[1] = (float)(dn[0] / (cnt * 4.0));   // /(cnt*TOP_K)     * W_NEG
            g_count = 0;                              // reset for graph replay
            g_barA  = 0;
            g_barB  = 0;
        }
    }
}

extern "C" void kernel_launch(void* const* d_in, const int* in_sizes, int n_in,
                              void* d_out, int out_size) {
    const float* ori;
    const float* logits;
    if (in_sizes[0] == BB * CF * SP) {
        ori    = (const float*)d_in[0];
        logits = (const float*)d_in[1];
    } else {
        ori    = (const float*)d_in[1];
        logits = (const float*)d_in[0];
    }
    float* out = (float*)d_out;

    k_fused<<<GRID, 256>>>(logits, ori, out);
}

// round 15
// speedup vs baseline: 1.0562x; 1.0562x over previous
#include <cuda_runtime.h>
#include <math.h>

#define BB 2
#define C 19
#define CP 20             // padded channels
#define H 128
#define W 128
#define HW (H*W)          // 16384
#define CF 256
#define SH 64
#define SW 64
#define SP (SH*SW)        // 4096
#define N2 (BB*SP)        // 8192
#define NPIX (BB*HW)      // 32768
#define NCHUNK 8          // feature channel chunks of 32
#define NBLK 128          // main-kernel blocks
#define SM_BLOCKS 128     // softmax blocks in K1
#define SPART_BLOCKS 256  // simpart blocks in K1

// Scratch (static device globals; no allocations)
__device__ float  g_prob2[NPIX*CP];      // padded probs [pixel][20], [19]=0
__device__ float  g_spart[NCHUNK*5*N2];  // [chunk*5+dir][b*SP+s]
__device__ float  g_sim[9*N2];           // [k][b*SP+s]
__device__ float  g_pos[6*NPIX];         // planes: 0=selfdot 1=E 2=SW 3=S 4=SE 5=sump
__device__ double g_partial[3*NBLK];
__device__ int    g_count = 0;           // k_main last-block counter
__device__ int    g_flagS = 0;           // softmax-done block counter
__device__ int    g_flagP = 0;           // simpart-done block counter

__device__ __forceinline__ void flag_arrive(int* flag) {
    __threadfence();
    __syncthreads();
    if (threadIdx.x == 0) atomicAdd(flag, 1);
}
__device__ __forceinline__ void flag_wait(int* flag, int target) {
    if (threadIdx.x == 0) {
        volatile int* vf = flag;
        while (*vf < target) __nanosleep(64);
    }
    __syncthreads();
}

// ---------------- work units ----------------
__device__ __forceinline__ void softmax_work(const float* __restrict__ logits, int idx) {
    int b = idx >> 14;
    int p = idx & (HW - 1);
    const float* x = logits + (size_t)b * C * HW + p;
    float v[CP];
    float m = -1e30f;
    #pragma unroll
    for (int c = 0; c < C; c++) { v[c] = x[(size_t)c * HW]; m = fmaxf(m, v[c]); }
    float s = 0.f;
    #pragma unroll
    for (int c = 0; c < C; c++) { v[c] = expf(v[c] - m); s += v[c]; }
    float inv = 1.f / s;
    #pragma unroll
    for (int c = 0; c < C; c++) v[c] *= inv;
    v[19] = 0.f;
    float4* o = reinterpret_cast<float4*>(g_prob2 + (size_t)idx * CP);
    #pragma unroll
    for (int q = 0; q < 5; q++)
        o[q] = make_float4(v[4*q], v[4*q+1], v[4*q+2], v[4*q+3]);
}

__device__ __forceinline__ void simpart_work(const float* __restrict__ feats,
                                             int idx, int chunk) {
    int b  = idx >> 12;
    int s  = idx & (SP - 1);
    int sh = s >> 6, sw = s & 63;

    bool eOK = (sw < SW-1), sOK = (sh < SH-1), wOK = (sw > 0);
    int dE  = eOK ? 1 : 0;
    int dSW = (sOK && wOK) ? (SW - 1) : 0;
    int dS  = sOK ? SW : 0;
    int dSE = (sOK && eOK) ? (SW + 1) : 0;

    const float* fb = feats + ((size_t)b * CF + chunk * 32) * SP + s;
    float a0 = 0.f, a1 = 0.f, a2 = 0.f, a3 = 0.f, a4 = 0.f;
    #pragma unroll
    for (int ch = 0; ch < 32; ch++) {
        const float* fp = fb + (size_t)ch * SP;
        float f = fp[0];
        float d;
        a0 += f * f;
        d = f - fp[dE];  a1 += d * d;
        d = f - fp[dSW]; a2 += d * d;
        d = f - fp[dS];  a3 += d * d;
        d = f - fp[dSE]; a4 += d * d;
    }
    g_spart[(chunk*5 + 0) * N2 + idx] = a0;
    g_spart[(chunk*5 + 1) * N2 + idx] = a1;
    g_spart[(chunk*5 + 2) * N2 + idx] = a2;
    g_spart[(chunk*5 + 3) * N2 + idx] = a3;
    g_spart[(chunk*5 + 4) * N2 + idx] = a4;
}

__device__ __forceinline__ float dot20(const float4* pc, int nidx) {
    const float4* qv = reinterpret_cast<const float4*>(g_prob2 + (size_t)nidx * CP);
    float d = 0.f;
    #pragma unroll
    for (int u = 0; u < 5; u++) {
        float4 qq = qv[u];
        d += pc[u].x*qq.x + pc[u].y*qq.y + pc[u].z*qq.z + pc[u].w*qq.w;
    }
    return d;
}

__device__ __forceinline__ void pos_work(int t) {
    int half = t >> 15;
    int idx  = t & (NPIX - 1);
    int p = idx & (HW - 1);
    int h = p >> 7, w = p & 127;

    const float4* cen = reinterpret_cast<const float4*>(g_prob2 + (size_t)idx * CP);
    float4 pc[5];
    #pragma unroll
    for (int u = 0; u < 5; u++) pc[u] = cen[u];

    if (half == 0) {
        float sump = 0.f, cdot = 0.f;
        #pragma unroll
        for (int u = 0; u < 5; u++) {
            sump += pc[u].x + pc[u].y + pc[u].z + pc[u].w;
            cdot += pc[u].x*pc[u].x + pc[u].y*pc[u].y + pc[u].z*pc[u].z + pc[u].w*pc[u].w;
        }
        g_pos[0*NPIX + idx] = cdot;
        g_pos[5*NPIX + idx] = sump;
        g_pos[1*NPIX + idx] = (w < W-1)           ? dot20(pc, idx + 1)     : 0.f;
        g_pos[2*NPIX + idx] = (h < H-1 && w > 0)  ? dot20(pc, idx + W - 1) : 0.f;
    } else {
        g_pos[3*NPIX + idx] = (h < H-1)            ? dot20(pc, idx + W)     : 0.f;
        g_pos[4*NPIX + idx] = (h < H-1 && w < W-1) ? dot20(pc, idx + W + 1) : 0.f;
    }
}

__device__ __forceinline__ void simfin_work(int idx) {
    int s  = idx & (SP - 1);
    int sh = s >> 6, sw = s & 63;

    float self = 0.f, fE = 0.f, fSW = 0.f, fS = 0.f, fSE = 0.f;
    #pragma unroll
    for (int cu = 0; cu < NCHUNK; cu++) {
        self += g_spart[(cu*5 + 0) * N2 + idx];
        fE   += g_spart[(cu*5 + 1) * N2 + idx];
        fSW  += g_spart[(cu*5 + 2) * N2 + idx];
        fS   += g_spart[(cu*5 + 3) * N2 + idx];
        fSE  += g_spart[(cu*5 + 4) * N2 + idx];
    }
    bool wOK = (sw > 0), eOK = (sw < SW-1), nOK = (sh > 0), sOK = (sh < SH-1);

    float bW = 0.f, bNE = 0.f, bN = 0.f, bNW = 0.f;
    #pragma unroll
    for (int cu = 0; cu < NCHUNK; cu++) {
        if (wOK)         bW  += g_spart[(cu*5 + 1) * N2 + idx - 1];
        if (nOK && eOK)  bNE += g_spart[(cu*5 + 2) * N2 + idx - SW + 1];
        if (nOK)         bN  += g_spart[(cu*5 + 3) * N2 + idx - SW];
        if (nOK && wOK)  bNW += g_spart[(cu*5 + 4) * N2 + idx - SW - 1];
    }
    g_sim[4*N2 + idx] = expf(-self);
    g_sim[5*N2 + idx] = eOK          ? expf(-fE)  : 0.f;
    g_sim[6*N2 + idx] = (sOK && wOK) ? expf(-fSW) : 0.f;
    g_sim[7*N2 + idx] = sOK          ? expf(-fS)  : 0.f;
    g_sim[8*N2 + idx] = (sOK && eOK) ? expf(-fSE) : 0.f;
    g_sim[3*N2 + idx] = wOK          ? expf(-bW)  : 0.f;
    g_sim[2*N2 + idx] = (nOK && eOK) ? expf(-bNE) : 0.f;
    g_sim[1*N2 + idx] = nOK          ? expf(-bN)  : 0.f;
    g_sim[0*N2 + idx] = (nOK && wOK) ? expf(-bNW) : 0.f;
}

// ============ K1: pipelined producer kernel (672 blocks) ============
// bids: [0,128) softmax -> flagS; [128,384) simpart -> flagP;
//       [384,640) posdots (wait flagS==128); [640,672) simfin (wait flagP==256)
__global__ void __launch_bounds__(256, 3)
k_pre(const float* __restrict__ logits, const float* __restrict__ feats) {
    int tid = threadIdx.x;
    int bid = blockIdx.x;

    if (bid < SM_BLOCKS) {
        softmax_work(logits, bid * 256 + tid);
        flag_arrive(&g_flagS);
    } else if (bid < SM_BLOCKS + SPART_BLOCKS) {
        int sblk = bid - SM_BLOCKS;           // 0..255
        int xb = sblk & 31, chunk = sblk >> 5;
        simpart_work(feats, xb * 256 + tid, chunk);
        flag_arrive(&g_flagP);
    } else if (bid < 640) {
        flag_wait(&g_flagS, SM_BLOCKS);
        pos_work((bid - 384) * 256 + tid);
    } else {
        flag_wait(&g_flagP, SPART_BLOCKS);
        simfin_work((bid - 640) * 256 + tid);
    }
}

// ============ K2: main + fused final ============
__global__ void k_main(const float* __restrict__ ori, float* __restrict__ out) {
    __shared__ float rp[256], rn[256], rc[256];
    __shared__ int   sh_last;

    int tid = threadIdx.x;
    int idx = blockIdx.x * 256 + tid;          // pixel index
    int b = idx >> 14;
    int p = idx & (HW - 1);
    int h = p >> 7, w = p & 127;
    int sh2 = h >> 1, sw2 = w >> 1;
    size_t sbase = (size_t)b * SP + sh2 * SW + sw2;

    bool nOKp = (h > 0), sOKp = (h < H-1), wOKp = (w > 0), eOKp = (w < W-1);

    float sump = g_pos[5*NPIX + idx];
    float pos[9];
    pos[4] = g_pos[0*NPIX + idx];
    pos[5] = eOKp          ? g_pos[1*NPIX + idx]         : 0.f;
    pos[3] = wOKp          ? g_pos[1*NPIX + idx - 1]     : 0.f;
    pos[7] = sOKp          ? g_pos[3*NPIX + idx]         : 0.f;
    pos[1] = nOKp          ? g_pos[3*NPIX + idx - W]     : 0.f;
    pos[6] = (sOKp && wOKp)? g_pos[2*NPIX + idx]         : 0.f;
    pos[2] = (nOKp && eOKp)? g_pos[2*NPIX + idx - W + 1] : 0.f;
    pos[8] = (sOKp && eOKp)? g_pos[4*NPIX + idx]         : 0.f;
    pos[0] = (nOKp && wOKp)? g_pos[4*NPIX + idx - W - 1] : 0.f;

    float simC = g_sim[4*N2 + sbase];
    float sim[9], neg[9];
    #pragma unroll
    for (int k = 0; k < 9; k++) {
        int dr = k / 3 - 1, dc = k % 3 - 1;
        int hn = h + dr, wn = w + dc;
        bool valid = (hn >= 0 && hn < H && wn >= 0 && wn < W);
        neg[k] = valid ? (sump - pos[k]) : 0.f;   // sumq==1 valid, 0 for pad
        if (valid) {
            int dsh = (hn >> 1) - sh2, dsw = (wn >> 1) - sw2;
            int ks = (dsh + 1) * 3 + (dsw + 1);
            sim[k] = (ks == 4) ? 1.0f : g_sim[ks * N2 + sbase];
        } else {
            sim[k] = simC;
        }
    }

    float ssum = 0.f;
    #pragma unroll
    for (int k = 0; k < 9; k++) ssum += sim[k];
    out[2 + idx] = ssum * (1.f / 9.f);

    // rank-based stable top-k (jax tie-breaking: lower index first)
    int r[9], a[9];
    #pragma unroll
    for (int k = 0; k < 9; k++) { r[k] = 0; a[k] = 0; }
    #pragma unroll
    for (int jj = 0; jj < 9; jj++) {
        #pragma unroll
        for (int kk = jj + 1; kk < 9; kk++) {
            bool l = sim[jj] < sim[kk];
            bool g = sim[jj] > sim[kk];
            r[kk] += !l;
            r[jj] += l;
            a[kk] += !g;
            a[jj] += g;
        }
    }
    float lp = 0.f, ln = 0.f;
    #pragma unroll
    for (int k = 0; k < 9; k++) {
        if (r[k] < 5) lp += sim[k] * (-pos[k]);
        if (a[k] < 4) ln += (1.f - sim[k]) * (-neg[k]);
    }

    float f0  = ori[(size_t)b * CF * SP + sh2 * SW + sw2];
    float msk = (f0 > 0.f) ? 1.f : 0.f;

    rp[tid] = msk * lp; rn[tid] = msk * ln; rc[tid] = msk;
    __syncthreads();
    #pragma unroll
    for (int o = 128; o > 0; o >>= 1) {
        if (tid < o) { rp[tid] += rp[tid + o]; rn[tid] += rn[tid + o]; rc[tid] += rc[tid + o]; }
        __syncthreads();
    }
    if (tid == 0) {
        g_partial[blockIdx.x]            = (double)rp[0];
        g_partial[NBLK + blockIdx.x]     = (double)rn[0];
        g_partial[2 * NBLK + blockIdx.x] = (double)rc[0];
        __threadfence();
        int v = atomicAdd(&g_count, 1);
        sh_last = (v == NBLK - 1) ? 1 : 0;
    }
    __syncthreads();

    if (sh_last) {
        __shared__ double dp[128], dn[128], dc2[128];
        if (tid < 128) {
            volatile double* gp = g_partial;
            dp[tid]  = gp[tid];
            dn[tid]  = gp[NBLK + tid];
            dc2[tid] = gp[2 * NBLK + tid];
        }
        __syncthreads();
        #pragma unroll
        for (int o = 64; o > 0; o >>= 1) {
            if (tid < o) { dp[tid] += dp[tid + o]; dn[tid] += dn[tid + o]; dc2[tid] += dc2[tid + o]; }
            __syncthreads();
        }
        if (tid == 0) {
            double cnt = dc2[0];
            out[0] = (float)(dp[0] / (cnt * 5.0));   // /(cnt*(TOP_K+1)) * W_POS
            out[1] = (float)(dn[0] / (cnt * 4.0));   // /(cnt*TOP_K)     * W_NEG
            g_count = 0;                              // reset for graph replay
            g_flagS = 0;
            g_flagP = 0;
        }
    }
}

extern "C" void kernel_launch(void* const* d_in, const int* in_sizes, int n_in,
                              void* d_out, int out_size) {
    const float* ori;
    const float* logits;
    if (in_sizes[0] == BB * CF * SP) {
        ori    = (const float*)d_in[0];
        logits = (const float*)d_in[1];
    } else {
        ori    = (const float*)d_in[1];
        logits = (const float*)d_in[0];
    }
    float* out = (float*)d_out;

    k_pre<<<672, 256>>>(logits, ori);     // pipelined: softmax||simpart -> posdots||simfin
    k_main<<<NBLK, 256>>>(ori, out);      // main + fused final (resets flags)
}